// round 14
// baseline (speedup 1.0000x reference)
#include <cuda_runtime.h>
#include <math.h>

// Problem dims
#define Tt 1024
#define Bb 64
#define Ii 256
#define Hh 512
#define Oo 128

// Scan grid: 128 CTAs, each owns 16 batches x 16 cols of BOTH layers
#define G_CTAS 128
#define RNN_THREADS 256

// ---------------- device scratch (no runtime allocation allowed) ----------------
__device__ float g_xproj[(size_t)Tt * Bb * Hh];   // x@W_ih0^T + b_ih0 + b_hh0, [t][b][h]
__device__ float g_h0[2][Bb * Hh];                // double-buffered layer-0 hidden
__device__ float g_h1[2][Bb * Hh];                // double-buffered layer-1 hidden
__device__ unsigned g_flag[G_CTAS * 32];          // per-CTA phase flags, 128B padded

// ---------------- packed f32x2 helpers ----------------
#define FMA2(acc, a, b) \
    asm("fma.rn.f32x2 %0, %1, %2, %0;" : "+l"(acc) : "l"(a), "l"(b))

__device__ __forceinline__ float f2sum(unsigned long long u) {
    float lo, hi;
    asm("mov.b64 {%0,%1}, %2;" : "=f"(lo), "=f"(hi) : "l"(u));
    return lo + hi;
}

// ---------------- cp.async (L2-direct; coherence-safe across SMs) ----------------
__device__ __forceinline__ void cpa16(unsigned s, const float* g) {
    asm volatile("cp.async.cg.shared.global [%0], [%1], 16;" :: "r"(s), "l"(g));
}

// ---------------- distributed-flag grid barrier (128 co-resident CTAs) ----------
__device__ __forceinline__ unsigned ld_acq(const unsigned* p) {
    unsigned v;
    asm volatile("ld.acquire.gpu.u32 %0, [%1];" : "=r"(v) : "l"(p) : "memory");
    return v;
}
__device__ __forceinline__ void st_rel(unsigned* p, unsigned v) {
    asm volatile("st.relaxed.gpu.u32 [%0], %1;" :: "l"(p), "r"(v) : "memory");
}

__device__ __forceinline__ void phase_barrier(int cta, unsigned tgt) {
    __syncthreads();
    if (threadIdx.x == 0) {
        __threadfence();
        st_rel(&g_flag[cta * 32], tgt);
    }
    if (threadIdx.x < G_CTAS) {
        const unsigned* f = &g_flag[threadIdx.x * 32];
        while ((int)(ld_acq(f) - tgt) < 0) { }
    }
    __syncthreads();
}

// Multi-value butterfly allreduce: on return v[0] holds, for lane L, the full
// 32-lane sum of original v[L]. 31 shfls total.
__device__ __forceinline__ void butterfly32(float (&v)[32], int ln) {
    #pragma unroll
    for (int m = 16; m >= 1; m >>= 1) {
        #pragma unroll
        for (int i = 0; i < m; ++i) {
            float a = v[i], b = v[i + m];
            float send = (ln & m) ? a : b;
            float recv = __shfl_xor_sync(0xffffffffu, send, m);
            v[i] = (ln & m) ? (b + recv) : (a + recv);
        }
    }
}

// =================================================================================
// Kernel 1: xproj[t][b][j] = sum_i x[b][t][i] * W_ih0[j][i] + b_ih0[j] + b_hh0[j]
// =================================================================================
__global__ void __launch_bounds__(256) xproj_kernel(
    const float* __restrict__ x, const float* __restrict__ W,
    const float* __restrict__ bih, const float* __restrict__ bhh)
{
    __shared__ float xs[64 * 68];
    __shared__ float ws[64 * 68];

    const int t   = blockIdx.y;
    const int n0  = blockIdx.x * 64;
    const int tid = threadIdx.x;
    const int tx  = tid & 15;
    const int ty  = tid >> 4;
    const int mi0 = ty * 4;
    const int ni0 = tx * 4;

    float acc[4][4] = {};

    for (int kc = 0; kc < 4; ++kc) {
        const int k0 = kc * 64;
        for (int idx = tid; idx < 1024; idx += 256) {
            int b  = idx >> 4;
            int c4 = idx & 15;
            float4 v = *reinterpret_cast<const float4*>(
                x + ((size_t)b * Tt + t) * Ii + k0 + c4 * 4);
            *reinterpret_cast<float4*>(xs + b * 68 + c4 * 4) = v;
        }
        for (int idx = tid; idx < 1024; idx += 256) {
            int nl = idx >> 4;
            int c4 = idx & 15;
            float4 v = *reinterpret_cast<const float4*>(
                W + (size_t)(n0 + nl) * Ii + k0 + c4 * 4);
            int k = c4 * 4;
            ws[(k + 0) * 68 + nl] = v.x;
            ws[(k + 1) * 68 + nl] = v.y;
            ws[(k + 2) * 68 + nl] = v.z;
            ws[(k + 3) * 68 + nl] = v.w;
        }
        __syncthreads();
        #pragma unroll 8
        for (int k = 0; k < 64; ++k) {
            float4 wv = *reinterpret_cast<const float4*>(ws + k * 68 + ni0);
            float x0 = xs[(mi0 + 0) * 68 + k];
            float x1 = xs[(mi0 + 1) * 68 + k];
            float x2 = xs[(mi0 + 2) * 68 + k];
            float x3 = xs[(mi0 + 3) * 68 + k];
            acc[0][0] += x0 * wv.x; acc[0][1] += x0 * wv.y; acc[0][2] += x0 * wv.z; acc[0][3] += x0 * wv.w;
            acc[1][0] += x1 * wv.x; acc[1][1] += x1 * wv.y; acc[1][2] += x1 * wv.z; acc[1][3] += x1 * wv.w;
            acc[2][0] += x2 * wv.x; acc[2][1] += x2 * wv.y; acc[2][2] += x2 * wv.z; acc[2][3] += x2 * wv.w;
            acc[3][0] += x3 * wv.x; acc[3][1] += x3 * wv.y; acc[3][2] += x3 * wv.z; acc[3][3] += x3 * wv.w;
        }
        __syncthreads();
    }

    float4 bias;
    bias.x = bih[n0 + ni0 + 0] + bhh[n0 + ni0 + 0];
    bias.y = bih[n0 + ni0 + 1] + bhh[n0 + ni0 + 1];
    bias.z = bih[n0 + ni0 + 2] + bhh[n0 + ni0 + 2];
    bias.w = bih[n0 + ni0 + 3] + bhh[n0 + ni0 + 3];
    #pragma unroll
    for (int i = 0; i < 4; ++i) {
        float4 o;
        o.x = acc[i][0] + bias.x;
        o.y = acc[i][1] + bias.y;
        o.z = acc[i][2] + bias.z;
        o.w = acc[i][3] + bias.w;
        *reinterpret_cast<float4*>(
            g_xproj + ((size_t)t * Bb + (mi0 + i)) * Hh + n0 + ni0) = o;
    }
}

// =================================================================================
// Kernel 2: persistent merged-layer scan, balanced at 768 FMA2/thread.
// Phase p, CTA (bt, ct) owns batches [16bt,+16) x cols [16ct,+16) of BOTH layers.
//   Phase 1 (hs1 = h1(p-2)): warps 0-3 do wh1 K[256:512) (helper partials -> smem),
//                            warps 4-7 do wh1 K[0:256)   (kept in registers)
//   Phase 2 (hs0 = h0(p-1)): warps 0-3 do W_hh0 (full K)  -> h0(p)
//                            warps 4-7 do W_ih1 (full K) + helper partials -> h1(p-1)
// cp.async: h1 group committed FIRST (phase-1 input), h0 streams under phase 1.
// =================================================================================
extern __shared__ float smf[];

__global__ void __launch_bounds__(RNN_THREADS, 1) rnn_kernel(
    const float* __restrict__ h_init,
    const float* __restrict__ W_hh0,
    const float* __restrict__ W_ih1, const float* __restrict__ b_ih1,
    const float* __restrict__ W_hh1, const float* __restrict__ b_hh1)
{
    const int tid = threadIdx.x;
    const int cta = blockIdx.x;
    const int w   = tid >> 5;
    const int ln  = tid & 31;
    const int B0  = (cta >> 5) * 16;     // batch tile base
    const int C0  = (cta & 31) * 16;     // col tile base (same cols for L0 & L1)
    const bool isL0w = (w < 4);
    const int wl = isL0w ? w : (w - 4);  // warp w pairs with warp w+4 (same tile)
    const int lb = (wl & 1) * 8;         // warp local batch base (0/8)
    const int cw = (wl >> 1) * 8;        // warp local col base (0/8)

    // SMEM: W0[16][512] | Wi1[16][512] | Wh1[16][512] | hs0[16][512] | hs1[16][512] | red[256]
    float* W0  = smf;
    float* Wi1 = smf + 8192;
    float* Wh1 = smf + 16384;
    float* hs0 = smf + 24576;
    float* hs1 = smf + 32768;
    float* red = smf + 40960;            // helper partials: [4 warps][32 lanes][2]

    const unsigned base = g_flag[cta * 32];

    // ---- load weight slices (K contiguous per col) ----
    {
        float4* d0 = reinterpret_cast<float4*>(W0);
        float4* d1 = reinterpret_cast<float4*>(Wi1);
        float4* d2 = reinterpret_cast<float4*>(Wh1);
        for (int i = tid; i < 16 * 128; i += RNN_THREADS) {
            int c = i >> 7, k4 = i & 127;
            size_t go = (size_t)(C0 + c) * Hh + k4 * 4;
            d0[i] = *reinterpret_cast<const float4*>(W_hh0 + go);
            d1[i] = *reinterpret_cast<const float4*>(W_ih1 + go);
            d2[i] = *reinterpret_cast<const float4*>(W_hh1 + go);
        }
    }
    // ---- init state (graph replays re-init every launch) ----
    {
        int i = cta * RNN_THREADS + tid;     // 32768 threads == Bb*Hh
        g_h0[0][i] = h_init[i];
        g_h1[0][i] = h_init[Bb * Hh + i];
    }
    phase_barrier(cta, base + 1);            // init complete

    // per-lane output mapping (flat acc idx = b*8+c): out0 b=ln>>3, out1 b=4+(ln>>3)
    const int ob0 = lb + (ln >> 3);
    const int ob1 = ob0 + 4;
    const int gc  = C0 + cw + (ln & 7);
    const float bias1 = b_ih1[gc] + b_hh1[gc];               // L1 warps only
    const float* xpa = g_xproj + (size_t)(B0 + ob0) * Hh + gc;
    const float* xpb = g_xproj + (size_t)(B0 + ob1) * Hh + gc;

    const unsigned hs0u = (unsigned)__cvta_generic_to_shared(hs0);
    const unsigned hs1u = (unsigned)__cvta_generic_to_shared(hs1);
    const int bhi = tid >> 7;                // stage addressing
    const int k4s = tid & 127;

    for (int p = 1; p <= Tt + 1; ++p) {
        const float* h0prev = g_h0[(p - 1) & 1];   // h0(p-1)
        float*       h0out  = g_h0[p & 1];         // h0(p)
        const float* h1prev = g_h1[p & 1];         // h1(p-2)
        float*       h1out  = g_h1[(p - 1) & 1];   // h1(p-1)

        float px0 = 0.f, px1 = 0.f;
        if (isL0w && p <= Tt) {                    // DRAM prefetch, hidden by FMAs
            size_t toff = (size_t)(p - 1) * (Bb * Hh);
            px0 = __ldcg(xpa + toff);
            px1 = __ldcg(xpb + toff);
        }

        // async stage: group A = h1 tile (phase-1 input), group B = h0 tile
        #pragma unroll
        for (int q = 0; q < 8; ++q) {
            int b = q * 2 + bhi;
            cpa16(hs1u + (unsigned)(b * 512 + k4s * 4) * 4u,
                  h1prev + (size_t)(B0 + b) * Hh + k4s * 4);
        }
        asm volatile("cp.async.commit_group;");
        #pragma unroll
        for (int q = 0; q < 8; ++q) {
            int b = q * 2 + bhi;
            cpa16(hs0u + (unsigned)(b * 512 + k4s * 4) * 4u,
                  h0prev + (size_t)(B0 + b) * Hh + k4s * 4);
        }
        asm volatile("cp.async.commit_group;");

        unsigned long long acc[64];
        #pragma unroll
        for (int i = 0; i < 64; ++i) acc[i] = 0ull;

        asm volatile("cp.async.wait_group 1;" ::: "memory");   // h1 tile ready
        __syncthreads();

        // ---- Phase 1: wh1 x hs1, K-split between paired warps ----
        {
            const int mbase = isL0w ? 2 : 0;       // L0 warps: K[256:512), L1: K[0:256)
            #pragma unroll
            for (int mm = 0; mm < 2; ++mm) {
                const int k = (mbase + mm) * 128 + ln * 4;
                ulonglong2 h2[8];
                #pragma unroll
                for (int b = 0; b < 8; ++b)
                    h2[b] = *reinterpret_cast<const ulonglong2*>(hs1 + (lb + b) * 512 + k);
                #pragma unroll
                for (int c = 0; c < 8; ++c) {
                    ulonglong2 w2 = *reinterpret_cast<const ulonglong2*>(Wh1 + (cw + c) * 512 + k);
                    #pragma unroll
                    for (int b = 0; b < 8; ++b) {
                        FMA2(acc[b * 8 + c], h2[b].x, w2.x);
                        FMA2(acc[b * 8 + c], h2[b].y, w2.y);
                    }
                }
            }
        }

        // L0 warps: reduce helper partials now and park them in smem
        if (isL0w) {
            float v[32];
            #pragma unroll
            for (int i = 0; i < 32; ++i) v[i] = f2sum(acc[i]);
            butterfly32(v, ln);
            red[w * 64 + ln * 2 + 0] = v[0];
            #pragma unroll
            for (int i = 0; i < 32; ++i) v[i] = f2sum(acc[32 + i]);
            butterfly32(v, ln);
            red[w * 64 + ln * 2 + 1] = v[0];
            #pragma unroll
            for (int i = 0; i < 64; ++i) acc[i] = 0ull;   // reuse for Phase 2
        }

        asm volatile("cp.async.wait_group 0;" ::: "memory");   // h0 tile ready
        __syncthreads();                                       // + publishes red[]

        // ---- Phase 2: full-K over hs0 (L0: W_hh0 -> h0(p); L1: W_ih1 += into acc) ----
        {
            const float* Wa = isL0w ? W0 : Wi1;
            #pragma unroll
            for (int m = 0; m < 4; ++m) {
                const int k = m * 128 + ln * 4;
                ulonglong2 h2[8];
                #pragma unroll
                for (int b = 0; b < 8; ++b)
                    h2[b] = *reinterpret_cast<const ulonglong2*>(hs0 + (lb + b) * 512 + k);
                #pragma unroll
                for (int c = 0; c < 8; ++c) {
                    ulonglong2 w2 = *reinterpret_cast<const ulonglong2*>(Wa + (cw + c) * 512 + k);
                    #pragma unroll
                    for (int b = 0; b < 8; ++b) {
                        FMA2(acc[b * 8 + c], h2[b].x, w2.x);
                        FMA2(acc[b * 8 + c], h2[b].y, w2.y);
                    }
                }
            }
        }

        // ---- reduce + activation + store ----
        float v[32];
        #pragma unroll
        for (int i = 0; i < 32; ++i) v[i] = f2sum(acc[i]);
        butterfly32(v, ln);
        float out0 = v[0];
        #pragma unroll
        for (int i = 0; i < 32; ++i) v[i] = f2sum(acc[32 + i]);
        butterfly32(v, ln);
        float out1 = v[0];

        if (isL0w) {
            if (p <= Tt) {
                h0out[(size_t)(B0 + ob0) * Hh + gc] = tanhf(out0 + px0);
                h0out[(size_t)(B0 + ob1) * Hh + gc] = tanhf(out1 + px1);
            }
        } else if (p > 1) {
            out0 += red[(w - 4) * 64 + ln * 2 + 0];
            out1 += red[(w - 4) * 64 + ln * 2 + 1];
            h1out[(size_t)(B0 + ob0) * Hh + gc] = tanhf(out0 + bias1);
            h1out[(size_t)(B0 + ob1) * Hh + gc] = tanhf(out1 + bias1);
        }

        phase_barrier(cta, base + 1 + p);
    }
}

// =================================================================================
// Kernel 3: out[b][o] = h1_final[b] . W_out[o] + b_out[o]   (h1(1024) is parity 0)
// =================================================================================
__global__ void __launch_bounds__(128) head_kernel(
    const float* __restrict__ W_out, const float* __restrict__ b_out,
    float* __restrict__ out)
{
    const int b = blockIdx.x;
    const int o = threadIdx.x;
    const float* h = g_h1[0] + b * Hh;
    const float* wv = W_out + (size_t)o * Hh;
    float acc = 0.f;
    #pragma unroll 8
    for (int k = 0; k < Hh; k += 4) {
        float4 hv = *reinterpret_cast<const float4*>(h + k);
        float4 wr = *reinterpret_cast<const float4*>(wv + k);
        acc += hv.x * wr.x + hv.y * wr.y + hv.z * wr.z + hv.w * wr.w;
    }
    out[b * Oo + o] = acc + b_out[o];
}

// =================================================================================
extern "C" void kernel_launch(void* const* d_in, const int* in_sizes, int n_in,
                              void* d_out, int out_size)
{
    (void)in_sizes; (void)n_in; (void)out_size;
    const float* x      = (const float*)d_in[0];
    const float* h0     = (const float*)d_in[1];
    const float* W_ih0  = (const float*)d_in[2];
    const float* b_ih0  = (const float*)d_in[3];
    const float* W_hh0  = (const float*)d_in[4];
    const float* b_hh0  = (const float*)d_in[5];
    const float* W_ih1  = (const float*)d_in[6];
    const float* b_ih1  = (const float*)d_in[7];
    const float* W_hh1  = (const float*)d_in[8];
    const float* b_hh1  = (const float*)d_in[9];
    const float* W_out  = (const float*)d_in[10];
    const float* b_out  = (const float*)d_in[11];
    float* out = (float*)d_out;

    // SMEM: 5 x (16x512 floats) + 256 floats partials = 41216 floats = 164864 B
    static int smem_set = 0;
    if (!smem_set) {
        cudaFuncSetAttribute(rnn_kernel,
                             cudaFuncAttributeMaxDynamicSharedMemorySize, 164864);
        smem_set = 1;
    }

    xproj_kernel<<<dim3(8, Tt), 256>>>(x, W_ih0, b_ih0, b_hh0);
    rnn_kernel<<<G_CTAS, RNN_THREADS, 164864>>>(h0, W_hh0, W_ih1, b_ih1, W_hh1, b_hh1);
    head_kernel<<<Bb, Oo>>>(W_out, b_out, out);
}

// round 15
// speedup vs baseline: 1.0849x; 1.0849x over previous
#include <cuda_runtime.h>
#include <math.h>

// Problem dims
#define Tt 1024
#define Bb 64
#define Ii 256
#define Hh 512
#define Oo 128

// Scan grid: 128 CTAs, each owns 16 batches x 16 cols of BOTH layers.
// Batch groups of 32 CTAs (same 16 batches) exchange h; groups are independent.
#define G_CTAS 128
#define RNN_THREADS 256

// ---------------- device scratch (no runtime allocation allowed) ----------------
__device__ float g_xproj[(size_t)Tt * Bb * Hh];   // x@W_ih0^T + b_ih0 + b_hh0, [t][b][h]
__device__ float g_h0[2][Bb * Hh];                // double-buffered layer-0 hidden
__device__ float g_h1[2][Bb * Hh];                // double-buffered layer-1 hidden
__device__ unsigned g_flag0[G_CTAS * 32];         // L0 pipeline flags (128B padded)
__device__ unsigned g_flag1[G_CTAS * 32];         // L1 pipeline flags

// ---------------- packed f32x2 helpers ----------------
#define FMA2(acc, a, b) \
    asm("fma.rn.f32x2 %0, %1, %2, %0;" : "+l"(acc) : "l"(a), "l"(b))

__device__ __forceinline__ float f2sum(unsigned long long u) {
    float lo, hi;
    asm("mov.b64 {%0,%1}, %2;" : "=f"(lo), "=f"(hi) : "l"(u));
    return lo + hi;
}

// ---------------- cp.async (L2-direct; coherence-safe across SMs) ----------------
__device__ __forceinline__ void cpa16(unsigned s, const float* g) {
    asm volatile("cp.async.cg.shared.global [%0], [%1], 16;" :: "r"(s), "l"(g));
}

__device__ __forceinline__ unsigned ld_acq(const unsigned* p) {
    unsigned v;
    asm volatile("ld.acquire.gpu.u32 %0, [%1];" : "=r"(v) : "l"(p) : "memory");
    return v;
}
__device__ __forceinline__ void st_rel(unsigned* p, unsigned v) {
    asm volatile("st.relaxed.gpu.u32 [%0], %1;" :: "l"(p), "r"(v) : "memory");
}
__device__ __forceinline__ void named_bar(int id) {
    asm volatile("bar.sync %0, 128;" :: "r"(id) : "memory");
}

// Multi-value butterfly allreduce: on return v[0] holds, for lane L, the full
// 32-lane sum of original v[L]. 31 shfls total.
__device__ __forceinline__ void butterfly32(float (&v)[32], int ln) {
    #pragma unroll
    for (int m = 16; m >= 1; m >>= 1) {
        #pragma unroll
        for (int i = 0; i < m; ++i) {
            float a = v[i], b = v[i + m];
            float send = (ln & m) ? a : b;
            float recv = __shfl_xor_sync(0xffffffffu, send, m);
            v[i] = (ln & m) ? (b + recv) : (a + recv);
        }
    }
}

// =================================================================================
// Kernel 1: xproj[t][b][j] = sum_i x[b][t][i] * W_ih0[j][i] + b_ih0[j] + b_hh0[j]
// =================================================================================
__global__ void __launch_bounds__(256) xproj_kernel(
    const float* __restrict__ x, const float* __restrict__ W,
    const float* __restrict__ bih, const float* __restrict__ bhh)
{
    __shared__ float xs[64 * 68];
    __shared__ float ws[64 * 68];

    const int t   = blockIdx.y;
    const int n0  = blockIdx.x * 64;
    const int tid = threadIdx.x;
    const int tx  = tid & 15;
    const int ty  = tid >> 4;
    const int mi0 = ty * 4;
    const int ni0 = tx * 4;

    float acc[4][4] = {};

    for (int kc = 0; kc < 4; ++kc) {
        const int k0 = kc * 64;
        for (int idx = tid; idx < 1024; idx += 256) {
            int b  = idx >> 4;
            int c4 = idx & 15;
            float4 v = *reinterpret_cast<const float4*>(
                x + ((size_t)b * Tt + t) * Ii + k0 + c4 * 4);
            *reinterpret_cast<float4*>(xs + b * 68 + c4 * 4) = v;
        }
        for (int idx = tid; idx < 1024; idx += 256) {
            int nl = idx >> 4;
            int c4 = idx & 15;
            float4 v = *reinterpret_cast<const float4*>(
                W + (size_t)(n0 + nl) * Ii + k0 + c4 * 4);
            int k = c4 * 4;
            ws[(k + 0) * 68 + nl] = v.x;
            ws[(k + 1) * 68 + nl] = v.y;
            ws[(k + 2) * 68 + nl] = v.z;
            ws[(k + 3) * 68 + nl] = v.w;
        }
        __syncthreads();
        #pragma unroll 8
        for (int k = 0; k < 64; ++k) {
            float4 wv = *reinterpret_cast<const float4*>(ws + k * 68 + ni0);
            float x0 = xs[(mi0 + 0) * 68 + k];
            float x1 = xs[(mi0 + 1) * 68 + k];
            float x2 = xs[(mi0 + 2) * 68 + k];
            float x3 = xs[(mi0 + 3) * 68 + k];
            acc[0][0] += x0 * wv.x; acc[0][1] += x0 * wv.y; acc[0][2] += x0 * wv.z; acc[0][3] += x0 * wv.w;
            acc[1][0] += x1 * wv.x; acc[1][1] += x1 * wv.y; acc[1][2] += x1 * wv.z; acc[1][3] += x1 * wv.w;
            acc[2][0] += x2 * wv.x; acc[2][1] += x2 * wv.y; acc[2][2] += x2 * wv.z; acc[2][3] += x2 * wv.w;
            acc[3][0] += x3 * wv.x; acc[3][1] += x3 * wv.y; acc[3][2] += x3 * wv.z; acc[3][3] += x3 * wv.w;
        }
        __syncthreads();
    }

    float4 bias;
    bias.x = bih[n0 + ni0 + 0] + bhh[n0 + ni0 + 0];
    bias.y = bih[n0 + ni0 + 1] + bhh[n0 + ni0 + 1];
    bias.z = bih[n0 + ni0 + 2] + bhh[n0 + ni0 + 2];
    bias.w = bih[n0 + ni0 + 3] + bhh[n0 + ni0 + 3];
    #pragma unroll
    for (int i = 0; i < 4; ++i) {
        float4 o;
        o.x = acc[i][0] + bias.x;
        o.y = acc[i][1] + bias.y;
        o.z = acc[i][2] + bias.z;
        o.w = acc[i][3] + bias.w;
        *reinterpret_cast<float4*>(
            g_xproj + ((size_t)t * Bb + (mi0 + i)) * Hh + n0 + ni0) = o;
    }
}

// =================================================================================
// Kernel 2: persistent scan, two decoupled warp-specialized pipelines per CTA.
//   L0 pipeline (warps 4-7, flags0): h0(p) = tanh(xproj[p-1] + h0(p-1)@W_hh0^T)
//   L1 pipeline (warps 0-3, flags1): h1(p) = tanh(h0(p)@W_ih1^T + h1(p-1)@W_hh1^T + b)
// flag0 = base0+1+s  <=>  h0(s) globally visible;  flag1 = base1+1+s <=> h1(s).
// L0 step p polls: flags0 >= base0+p (h0(p-1) ready)
//                  flags1 >= base1+p-1 (L1 done step p-2 -> safe to overwrite buffer)
// L1 step p polls: flags0 >= base0+1+p (h0(p)), flags1 >= base1+p (h1(p-1); also
//                  guarantees group done reading the h1 buffer being overwritten).
// Exchanges are batch-group local (32 CTAs). Named barriers per half.
// =================================================================================
extern __shared__ float smf[];

__global__ void __launch_bounds__(RNN_THREADS, 1) rnn_kernel(
    const float* __restrict__ h_init,
    const float* __restrict__ W_hh0,
    const float* __restrict__ W_ih1, const float* __restrict__ b_ih1,
    const float* __restrict__ W_hh1, const float* __restrict__ b_hh1)
{
    const int tid = threadIdx.x;
    const int cta = blockIdx.x;
    const int ln  = tid & 31;
    const int wl  = (tid >> 5) & 3;      // warp index within half
    const bool isL0 = (tid >= 128);      // hi-wid warps: latency-critical h0 chain
    const int tpr = tid & 127;           // thread rank within half
    const int group = cta >> 5;          // batch group (4 groups of 32 CTAs)
    const int B0  = group * 16;
    const int C0  = (cta & 31) * 16;
    const int lb  = (wl & 1) * 8;        // warp local batch base
    const int cw  = (wl >> 1) * 8;       // warp local col base

    // SMEM: W0 | Wi1 | Wh1 | hsA (L0: h0 stage) | hsB (L1: h0 stage) | hsC (L1: h1 stage)
    float* W0  = smf;
    float* Wi1 = smf + 8192;
    float* Wh1 = smf + 16384;
    float* hsA = smf + 24576;
    float* hsB = smf + 32768;
    float* hsC = smf + 40960;

    const unsigned base0 = g_flag0[cta * 32];   // uniform across CTAs between launches
    const unsigned base1 = g_flag1[cta * 32];

    // ---- load weight slices (K contiguous per col) ----
    {
        float4* d0 = reinterpret_cast<float4*>(W0);
        float4* d1 = reinterpret_cast<float4*>(Wi1);
        float4* d2 = reinterpret_cast<float4*>(Wh1);
        for (int i = tid; i < 16 * 128; i += RNN_THREADS) {
            int c = i >> 7, k4 = i & 127;
            size_t go = (size_t)(C0 + c) * Hh + k4 * 4;
            d0[i] = *reinterpret_cast<const float4*>(W_hh0 + go);
            d1[i] = *reinterpret_cast<const float4*>(W_ih1 + go);
            d2[i] = *reinterpret_cast<const float4*>(W_hh1 + go);
        }
    }
    // ---- init state: each CTA writes ITS GROUP's batch rows only (group-local) ----
    {
        // group slice: rows [B0, B0+16) x 512 = 2048 float4; CTA covers member slice
        float4* h0d = reinterpret_cast<float4*>(g_h0[0] + (size_t)B0 * Hh);
        float4* h1d = reinterpret_cast<float4*>(g_h1[0] + (size_t)B0 * Hh);
        const float4* s0 = reinterpret_cast<const float4*>(h_init + (size_t)B0 * Hh);
        const float4* s1 = reinterpret_cast<const float4*>(h_init + (size_t)(Bb + B0) * Hh);
        int mem = cta & 31;                        // 32 members x 64 float4 each
        for (int q = 0; q < 8; ++q) {
            int i = mem * 64 + (q * 8 + (tid >> 5)) * ((64) / 8) + 0; // unused; simple below
        }
        for (int i = mem * 64 + (tid >> 2); i < (mem + 1) * 64 * 1; i += 64) { }
        // simple strided cover of member block [mem*64, mem*64+64) x ... use flat:
        for (int i = tid; i < 2048 / 32; i += RNN_THREADS) { }
        // flat: 2048 float4 across 32 members -> 64 per member; 256 threads cover 64
        // entries with stride (only tid<64 write, coalesced)
        if (tid < 64) {
            int i = mem * 64 + tid;
            h0d[i] = s0[i];
            h1d[i] = s1[i];
        }
    }
    __syncthreads();
    if (tid == 0) {
        __threadfence();
        st_rel(&g_flag0[cta * 32], base0 + 1);   // h0(0) visible
        st_rel(&g_flag1[cta * 32], base1 + 1);   // h1(0) visible
    }

    // per-lane output mapping (flat acc idx = b*8+c)
    const int ob0 = lb + (ln >> 3);
    const int ob1 = ob0 + 4;
    const int gc  = C0 + cw + (ln & 7);

    if (isL0) {
        // ================= L0 pipeline: warps 4-7, named barrier 1 =================
        const float* xpa = g_xproj + (size_t)(B0 + ob0) * Hh + gc;
        const float* xpb = g_xproj + (size_t)(B0 + ob1) * Hh + gc;
        const unsigned hsAu = (unsigned)__cvta_generic_to_shared(hsA);

        for (int p = 1; p <= Tt; ++p) {
            if (tpr < 32) {
                const unsigned* f0 = &g_flag0[(group * 32 + tpr) * 32];
                const unsigned* f1 = &g_flag1[(group * 32 + tpr) * 32];
                unsigned t0 = base0 + p;        // h0(p-1) ready
                unsigned t1 = base1 + p - 1;    // L1 done step p-2 (buffer safe)
                while ((int)(ld_acq(f0) - t0) < 0 || (int)(ld_acq(f1) - t1) < 0) { }
            }
            named_bar(1);

            const float* h0prev = g_h0[(p - 1) & 1];
            float*       h0out  = g_h0[p & 1];
            #pragma unroll
            for (int q = 0; q < 16; ++q) {
                int idx = q * 128 + tpr;
                int b = idx >> 7, k4 = idx & 127;
                cpa16(hsAu + (unsigned)(b * 512 + k4 * 4) * 4u,
                      h0prev + (size_t)(B0 + b) * Hh + k4 * 4);
            }
            asm volatile("cp.async.commit_group;");

            const size_t toff = (size_t)(p - 1) * (Bb * Hh);
            float px0 = __ldcg(xpa + toff);
            float px1 = __ldcg(xpb + toff);

            asm volatile("cp.async.wait_group 0;" ::: "memory");
            named_bar(1);

            unsigned long long acc[64];
            #pragma unroll
            for (int i = 0; i < 64; ++i) acc[i] = 0ull;

            #pragma unroll
            for (int m = 0; m < 4; ++m) {
                const int k = m * 128 + ln * 4;
                ulonglong2 h2[8];
                #pragma unroll
                for (int b = 0; b < 8; ++b)
                    h2[b] = *reinterpret_cast<const ulonglong2*>(hsA + (lb + b) * 512 + k);
                #pragma unroll
                for (int c = 0; c < 8; ++c) {
                    ulonglong2 w2 = *reinterpret_cast<const ulonglong2*>(W0 + (cw + c) * 512 + k);
                    #pragma unroll
                    for (int b = 0; b < 8; ++b) {
                        FMA2(acc[b * 8 + c], h2[b].x, w2.x);
                        FMA2(acc[b * 8 + c], h2[b].y, w2.y);
                    }
                }
            }

            float v[32];
            #pragma unroll
            for (int i = 0; i < 32; ++i) v[i] = f2sum(acc[i]);
            butterfly32(v, ln);
            float out0 = v[0];
            #pragma unroll
            for (int i = 0; i < 32; ++i) v[i] = f2sum(acc[32 + i]);
            butterfly32(v, ln);
            float out1 = v[0];

            h0out[(size_t)(B0 + ob0) * Hh + gc] = tanhf(out0 + px0);
            h0out[(size_t)(B0 + ob1) * Hh + gc] = tanhf(out1 + px1);

            named_bar(1);
            if (tpr == 0) {
                __threadfence();
                st_rel(&g_flag0[cta * 32], base0 + 1 + p);
            }
        }
    } else {
        // ================= L1 pipeline: warps 0-3, named barrier 2 =================
        const float bias1 = b_ih1[gc] + b_hh1[gc];
        const unsigned hsBu = (unsigned)__cvta_generic_to_shared(hsB);
        const unsigned hsCu = (unsigned)__cvta_generic_to_shared(hsC);

        for (int p = 1; p <= Tt; ++p) {
            if (tpr < 32) {
                const unsigned* f0 = &g_flag0[(group * 32 + tpr) * 32];
                const unsigned* f1 = &g_flag1[(group * 32 + tpr) * 32];
                unsigned t0 = base0 + 1 + p;    // h0(p) ready
                unsigned t1 = base1 + p;        // h1(p-1) ready (also buffer safety)
                while ((int)(ld_acq(f0) - t0) < 0 || (int)(ld_acq(f1) - t1) < 0) { }
            }
            named_bar(2);

            const float* h0cur  = g_h0[p & 1];         // h0(p)
            const float* h1prev = g_h1[(p - 1) & 1];   // h1(p-1)
            float*       h1out  = g_h1[p & 1];         // h1(p)
            #pragma unroll
            for (int q = 0; q < 16; ++q) {
                int idx = q * 128 + tpr;
                int b = idx >> 7, k4 = idx & 127;
                cpa16(hsBu + (unsigned)(b * 512 + k4 * 4) * 4u,
                      h0cur + (size_t)(B0 + b) * Hh + k4 * 4);
                cpa16(hsCu + (unsigned)(b * 512 + k4 * 4) * 4u,
                      h1prev + (size_t)(B0 + b) * Hh + k4 * 4);
            }
            asm volatile("cp.async.commit_group;");
            asm volatile("cp.async.wait_group 0;" ::: "memory");
            named_bar(2);

            unsigned long long acc[64];
            #pragma unroll
            for (int i = 0; i < 64; ++i) acc[i] = 0ull;

            #pragma unroll
            for (int m = 0; m < 4; ++m) {
                const int k = m * 128 + ln * 4;
                ulonglong2 h2[8];
                #pragma unroll
                for (int b = 0; b < 8; ++b)
                    h2[b] = *reinterpret_cast<const ulonglong2*>(hsB + (lb + b) * 512 + k);
                #pragma unroll
                for (int c = 0; c < 8; ++c) {
                    ulonglong2 w2 = *reinterpret_cast<const ulonglong2*>(Wi1 + (cw + c) * 512 + k);
                    #pragma unroll
                    for (int b = 0; b < 8; ++b) {
                        FMA2(acc[b * 8 + c], h2[b].x, w2.x);
                        FMA2(acc[b * 8 + c], h2[b].y, w2.y);
                    }
                }
            }
            #pragma unroll
            for (int m = 0; m < 4; ++m) {
                const int k = m * 128 + ln * 4;
                ulonglong2 h2[8];
                #pragma unroll
                for (int b = 0; b < 8; ++b)
                    h2[b] = *reinterpret_cast<const ulonglong2*>(hsC + (lb + b) * 512 + k);
                #pragma unroll
                for (int c = 0; c < 8; ++c) {
                    ulonglong2 w2 = *reinterpret_cast<const ulonglong2*>(Wh1 + (cw + c) * 512 + k);
                    #pragma unroll
                    for (int b = 0; b < 8; ++b) {
                        FMA2(acc[b * 8 + c], h2[b].x, w2.x);
                        FMA2(acc[b * 8 + c], h2[b].y, w2.y);
                    }
                }
            }

            float v[32];
            #pragma unroll
            for (int i = 0; i < 32; ++i) v[i] = f2sum(acc[i]);
            butterfly32(v, ln);
            float out0 = v[0];
            #pragma unroll
            for (int i = 0; i < 32; ++i) v[i] = f2sum(acc[32 + i]);
            butterfly32(v, ln);
            float out1 = v[0];

            h1out[(size_t)(B0 + ob0) * Hh + gc] = tanhf(out0 + bias1);
            h1out[(size_t)(B0 + ob1) * Hh + gc] = tanhf(out1 + bias1);

            named_bar(2);
            if (tpr == 0) {
                __threadfence();
                st_rel(&g_flag1[cta * 32], base1 + 1 + p);
            }
        }
    }
}

// =================================================================================
// Kernel 3: out[b][o] = h1(1024)[b] . W_out[o] + b_out[o]   (h1(1024) is parity 0)
// =================================================================================
__global__ void __launch_bounds__(128) head_kernel(
    const float* __restrict__ W_out, const float* __restrict__ b_out,
    float* __restrict__ out)
{
    const int b = blockIdx.x;
    const int o = threadIdx.x;
    const float* h = g_h1[0] + b * Hh;
    const float* wv = W_out + (size_t)o * Hh;
    float acc = 0.f;
    #pragma unroll 8
    for (int k = 0; k < Hh; k += 4) {
        float4 hv = *reinterpret_cast<const float4*>(h + k);
        float4 wr = *reinterpret_cast<const float4*>(wv + k);
        acc += hv.x * wr.x + hv.y * wr.y + hv.z * wr.z + hv.w * wr.w;
    }
    out[b * Oo + o] = acc + b_out[o];
}

// =================================================================================
extern "C" void kernel_launch(void* const* d_in, const int* in_sizes, int n_in,
                              void* d_out, int out_size)
{
    (void)in_sizes; (void)n_in; (void)out_size;
    const float* x      = (const float*)d_in[0];
    const float* h0     = (const float*)d_in[1];
    const float* W_ih0  = (const float*)d_in[2];
    const float* b_ih0  = (const float*)d_in[3];
    const float* W_hh0  = (const float*)d_in[4];
    const float* b_hh0  = (const float*)d_in[5];
    const float* W_ih1  = (const float*)d_in[6];
    const float* b_ih1  = (const float*)d_in[7];
    const float* W_hh1  = (const float*)d_in[8];
    const float* b_hh1  = (const float*)d_in[9];
    const float* W_out  = (const float*)d_in[10];
    const float* b_out  = (const float*)d_in[11];
    float* out = (float*)d_out;

    // SMEM: 6 x (16x512 floats) = 49152 floats = 192 KB
    static int smem_set = 0;
    if (!smem_set) {
        cudaFuncSetAttribute(rnn_kernel,
                             cudaFuncAttributeMaxDynamicSharedMemorySize, 196608);
        smem_set = 1;
    }

    xproj_kernel<<<dim3(8, Tt), 256>>>(x, W_ih0, b_ih0, b_hh0);
    rnn_kernel<<<G_CTAS, RNN_THREADS, 196608>>>(h0, W_hh0, W_ih1, b_ih1, W_hh1, b_hh1);
    head_kernel<<<Bb, Oo>>>(W_out, b_out, out);
}